// round 2
// baseline (speedup 1.0000x reference)
#include <cuda_runtime.h>
#include <math.h>

// Problem constants (fixed by the reference's setup)
#define N_IN 1000000
#define M_NODES 2000000
#define S0 (2 * N_IN + 2)
#define ILP 4   // nodes per thread; M_NODES % (ILP) == 0

// Scratch (no cudaMalloc allowed): encoded input + two ping-pong M-buffers
__device__ float g_enc[S0];
__device__ float g_bufA[M_NODES];
__device__ float g_bufB[M_NODES];

// log(1 - exp(x)) for x <= 0, stable (Maechler 2012), matching reference
__device__ __forceinline__ float log1mexp_f(float x) {
    const float NLOG2 = -0.69314718056f;
    if (x > NLOG2) {
        return logf(-expm1f(x));     // x in (-log2, 0]; x=0 -> log(0) = -inf
    } else {
        return log1pf(-expf(x));
    }
}

__global__ void encode_kernel(const float* __restrict__ pos) {
    int i = blockIdx.x * blockDim.x + threadIdx.x;
    if (i == 0) {
        g_enc[0] = -INFINITY;  // literal False
        g_enc[1] = 0.0f;       // literal True
    }
    if (i < N_IN) {
        float p = pos[i];
        g_enc[2 + 2 * i] = p;
        g_enc[3 + 2 * i] = log1mexp_f(p);
    }
}

// product layer: out[m] = sum of 4 gathered log-probs. ILP x4 nodes/thread.
__global__ void __launch_bounds__(256) product_kernel(
        const float* __restrict__ src,
        const int4* __restrict__ ptrs,
        float4* __restrict__ dst) {
    int t = blockIdx.x * blockDim.x + threadIdx.x;   // one float4 of output
    int base = t * ILP;
    if (base >= M_NODES) return;

    int4 p0 = ptrs[base + 0];
    int4 p1 = ptrs[base + 1];
    int4 p2 = ptrs[base + 2];
    int4 p3 = ptrs[base + 3];

    // issue all 16 gathers before consuming (MLP)
    float a0 = __ldg(src + p0.x), b0 = __ldg(src + p0.y), c0 = __ldg(src + p0.z), d0 = __ldg(src + p0.w);
    float a1 = __ldg(src + p1.x), b1 = __ldg(src + p1.y), c1 = __ldg(src + p1.z), d1 = __ldg(src + p1.w);
    float a2 = __ldg(src + p2.x), b2 = __ldg(src + p2.y), c2 = __ldg(src + p2.z), d2 = __ldg(src + p2.w);
    float a3 = __ldg(src + p3.x), b3 = __ldg(src + p3.y), c3 = __ldg(src + p3.z), d3 = __ldg(src + p3.w);

    float4 r;
    r.x = (a0 + b0) + (c0 + d0);
    r.y = (a1 + b1) + (c1 + d1);
    r.z = (a2 + b2) + (c2 + d2);
    r.w = (a3 + b3) + (c3 + d3);
    dst[t] = r;
}

// 4-way logsumexp with 1e-15 floor, max detached. ILP x4 nodes/thread.
__device__ __forceinline__ float lse4(float a, float b, float c, float d) {
    float mx = fmaxf(fmaxf(a, b), fmaxf(c, d));
    if (mx == -INFINITY) return -INFINITY;   // reference nan_to_num path
    float s = __expf(a - mx) + __expf(b - mx) + __expf(c - mx) + __expf(d - mx);
    return __logf(s + 1e-15f) + mx;
}

__global__ void __launch_bounds__(256) sum_kernel(
        const float* __restrict__ src,
        const int4* __restrict__ ptrs,
        float4* __restrict__ dst) {
    int t = blockIdx.x * blockDim.x + threadIdx.x;
    int base = t * ILP;
    if (base >= M_NODES) return;

    int4 p0 = ptrs[base + 0];
    int4 p1 = ptrs[base + 1];
    int4 p2 = ptrs[base + 2];
    int4 p3 = ptrs[base + 3];

    float a0 = __ldg(src + p0.x), b0 = __ldg(src + p0.y), c0 = __ldg(src + p0.z), d0 = __ldg(src + p0.w);
    float a1 = __ldg(src + p1.x), b1 = __ldg(src + p1.y), c1 = __ldg(src + p1.z), d1 = __ldg(src + p1.w);
    float a2 = __ldg(src + p2.x), b2 = __ldg(src + p2.y), c2 = __ldg(src + p2.z), d2 = __ldg(src + p2.w);
    float a3 = __ldg(src + p3.x), b3 = __ldg(src + p3.y), c3 = __ldg(src + p3.z), d3 = __ldg(src + p3.w);

    float4 r;
    r.x = lse4(a0, b0, c0, d0);
    r.y = lse4(a1, b1, c1, d1);
    r.z = lse4(a2, b2, c2, d2);
    r.w = lse4(a3, b3, c3, d3);
    dst[t] = r;
}

extern "C" void kernel_launch(void* const* d_in, const int* in_sizes, int n_in,
                              void* d_out, int out_size) {
    const float* pos   = (const float*)d_in[0];
    const int4*  ptrs0 = (const int4*)d_in[1];
    const int4*  ptrs1 = (const int4*)d_in[2];
    const int4*  ptrs2 = (const int4*)d_in[3];
    const int4*  ptrs3 = (const int4*)d_in[4];
    // d_in[5] (csr = repeat(arange(M),4)) is implicit in the layout.
    float* out = (float*)d_out;

    float* enc;  cudaGetSymbolAddress((void**)&enc,  g_enc);
    float* bufA; cudaGetSymbolAddress((void**)&bufA, g_bufA);
    float* bufB; cudaGetSymbolAddress((void**)&bufB, g_bufB);

    const int T = 256;
    const int blocksEnc = (N_IN + T - 1) / T;
    const int threadsM  = M_NODES / ILP;
    const int blocksM   = (threadsM + T - 1) / T;

    encode_kernel<<<blocksEnc, T>>>(pos);
    product_kernel<<<blocksM, T>>>(enc,  ptrs0, (float4*)bufA);
    sum_kernel    <<<blocksM, T>>>(bufA, ptrs1, (float4*)bufB);
    product_kernel<<<blocksM, T>>>(bufB, ptrs2, (float4*)bufA);
    sum_kernel    <<<blocksM, T>>>(bufA, ptrs3, (float4*)out);
}

// round 3
// speedup vs baseline: 1.0437x; 1.0437x over previous
#include <cuda_runtime.h>
#include <math.h>

// Problem constants (fixed by the reference's setup)
#define N_IN 1000000
#define M_NODES 2000000
#define S0 (2 * N_IN + 2)

// Scratch (no cudaMalloc allowed): encoded input + two ping-pong M-buffers
__device__ float g_enc[S0];
__device__ float g_bufA[M_NODES];
__device__ float g_bufB[M_NODES];

// log(1 - exp(x)) for x <= 0, stable (Maechler 2012), matching reference
__device__ __forceinline__ float log1mexp_f(float x) {
    const float NLOG2 = -0.69314718056f;
    if (x > NLOG2) {
        return logf(-expm1f(x));     // x in (-log2, 0]; x=0 -> log(0) = -inf
    } else {
        return log1pf(-expf(x));
    }
}

__global__ void encode_kernel(const float* __restrict__ pos) {
    int i = blockIdx.x * blockDim.x + threadIdx.x;
    if (i == 0) {
        g_enc[0] = -INFINITY;  // literal False
        g_enc[1] = 0.0f;       // literal True
    }
    if (i < N_IN) {
        float p = pos[i];
        g_enc[2 + 2 * i] = p;
        g_enc[3 + 2 * i] = log1mexp_f(p);
    }
}

// Gather with L1-bypass: random 4B gathers have ~3% L1 hit rate; skip the fill.
__device__ __forceinline__ float gcg(const float* p) { return __ldcg(p); }

// product layer: out[m] = sum of 4 gathered log-probs
__global__ void __launch_bounds__(256) product_kernel(
        const float* __restrict__ src,
        const int4* __restrict__ ptrs,
        float* __restrict__ dst) {
    int m = blockIdx.x * blockDim.x + threadIdx.x;
    if (m >= M_NODES) return;
    int4 p = __ldcs(ptrs + m);          // streaming: touch-once pointer data
    float a = gcg(src + p.x);
    float b = gcg(src + p.y);
    float c = gcg(src + p.z);
    float d = gcg(src + p.w);
    dst[m] = (a + b) + (c + d);
}

// sum layer: 4-way logsumexp with 1e-15 floor, max detached.
__global__ void __launch_bounds__(256) sum_kernel(
        const float* __restrict__ src,
        const int4* __restrict__ ptrs,
        float* __restrict__ dst) {
    int m = blockIdx.x * blockDim.x + threadIdx.x;
    if (m >= M_NODES) return;
    int4 p = __ldcs(ptrs + m);
    float a = gcg(src + p.x);
    float b = gcg(src + p.y);
    float c = gcg(src + p.z);
    float d = gcg(src + p.w);
    float mx = fmaxf(fmaxf(a, b), fmaxf(c, d));
    float out;
    if (mx == -INFINITY) {
        out = -INFINITY;                // reference nan_to_num path
    } else {
        float s = __expf(a - mx) + __expf(b - mx) + __expf(c - mx) + __expf(d - mx);
        out = __logf(s + 1e-15f) + mx;
    }
    dst[m] = out;
}

extern "C" void kernel_launch(void* const* d_in, const int* in_sizes, int n_in,
                              void* d_out, int out_size) {
    const float* pos   = (const float*)d_in[0];
    const int4*  ptrs0 = (const int4*)d_in[1];
    const int4*  ptrs1 = (const int4*)d_in[2];
    const int4*  ptrs2 = (const int4*)d_in[3];
    const int4*  ptrs3 = (const int4*)d_in[4];
    // d_in[5] (csr = repeat(arange(M),4)) is implicit in the layout.
    float* out = (float*)d_out;

    float* enc;  cudaGetSymbolAddress((void**)&enc,  g_enc);
    float* bufA; cudaGetSymbolAddress((void**)&bufA, g_bufA);
    float* bufB; cudaGetSymbolAddress((void**)&bufB, g_bufB);

    const int T = 256;
    const int blocksEnc = (N_IN + T - 1) / T;
    const int blocksM   = (M_NODES + T - 1) / T;

    encode_kernel<<<blocksEnc, T>>>(pos);
    product_kernel<<<blocksM, T>>>(enc,  ptrs0, bufA);
    sum_kernel    <<<blocksM, T>>>(bufA, ptrs1, bufB);
    product_kernel<<<blocksM, T>>>(bufB, ptrs2, bufA);
    sum_kernel    <<<blocksM, T>>>(bufA, ptrs3, out);
}

// round 4
// speedup vs baseline: 1.0460x; 1.0022x over previous
#include <cuda_runtime.h>
#include <math.h>

// Problem constants (fixed by the reference's setup)
#define N_IN 1000000
#define M_NODES 2000000
#define S0 (2 * N_IN + 2)

// Scratch (no cudaMalloc allowed): encoded input + two ping-pong M-buffers
__device__ float g_enc[S0];
__device__ float g_bufA[M_NODES];
__device__ float g_bufB[M_NODES];

// log(1 - exp(x)) for x <= 0, stable (Maechler 2012), matching reference
__device__ __forceinline__ float log1mexp_f(float x) {
    const float NLOG2 = -0.69314718056f;
    if (x > NLOG2) {
        return logf(-expm1f(x));     // x in (-log2, 0]; x=0 -> log(0) = -inf
    } else {
        return log1pf(-expf(x));
    }
}

__global__ void encode_kernel(const float* __restrict__ pos) {
    int i = blockIdx.x * blockDim.x + threadIdx.x;
    if (i == 0) {
        g_enc[0] = -INFINITY;  // literal False
        g_enc[1] = 0.0f;       // literal True
    }
    if (i < N_IN) {
        float p = pos[i];
        g_enc[2 + 2 * i] = p;
        g_enc[3 + 2 * i] = log1mexp_f(p);
    }
}

// Gather with L1-bypass: random 4B gathers have ~3% L1 hit rate; skip the fill.
__device__ __forceinline__ float gcg(const float* p) { return __ldcg(p); }

// product layer: out[m] = sum of 4 gathered log-probs
__global__ void __launch_bounds__(512) product_kernel(
        const float* __restrict__ src,
        const int4* __restrict__ ptrs,
        float* __restrict__ dst) {
    int m = blockIdx.x * blockDim.x + threadIdx.x;
    if (m >= M_NODES) return;
    int4 p = __ldcs(ptrs + m);          // streaming: touch-once pointer data
    float a = gcg(src + p.x);
    float b = gcg(src + p.y);
    float c = gcg(src + p.z);
    float d = gcg(src + p.w);
    __stcg(dst + m, (a + b) + (c + d)); // output re-read only via L2 gathers
}

// sum layer: 4-way logsumexp with 1e-15 floor, max detached.
__global__ void __launch_bounds__(512) sum_kernel(
        const float* __restrict__ src,
        const int4* __restrict__ ptrs,
        float* __restrict__ dst) {
    int m = blockIdx.x * blockDim.x + threadIdx.x;
    if (m >= M_NODES) return;
    int4 p = __ldcs(ptrs + m);
    float a = gcg(src + p.x);
    float b = gcg(src + p.y);
    float c = gcg(src + p.z);
    float d = gcg(src + p.w);
    float mx = fmaxf(fmaxf(a, b), fmaxf(c, d));
    float out;
    if (mx == -INFINITY) {
        out = -INFINITY;                // reference nan_to_num path
    } else {
        float s = __expf(a - mx) + __expf(b - mx) + __expf(c - mx) + __expf(d - mx);
        out = __logf(s + 1e-15f) + mx;
    }
    __stcg(dst + m, out);
}

extern "C" void kernel_launch(void* const* d_in, const int* in_sizes, int n_in,
                              void* d_out, int out_size) {
    const float* pos   = (const float*)d_in[0];
    const int4*  ptrs0 = (const int4*)d_in[1];
    const int4*  ptrs1 = (const int4*)d_in[2];
    const int4*  ptrs2 = (const int4*)d_in[3];
    const int4*  ptrs3 = (const int4*)d_in[4];
    // d_in[5] (csr = repeat(arange(M),4)) is implicit in the layout.
    float* out = (float*)d_out;

    float* enc;  cudaGetSymbolAddress((void**)&enc,  g_enc);
    float* bufA; cudaGetSymbolAddress((void**)&bufA, g_bufA);
    float* bufB; cudaGetSymbolAddress((void**)&bufB, g_bufB);

    const int T = 512;
    const int blocksEnc = (N_IN + T - 1) / T;
    const int blocksM   = (M_NODES + T - 1) / T;

    encode_kernel<<<blocksEnc, T>>>(pos);
    product_kernel<<<blocksM, T>>>(enc,  ptrs0, bufA);
    sum_kernel    <<<blocksM, T>>>(bufA, ptrs1, bufB);
    product_kernel<<<blocksM, T>>>(bufB, ptrs2, bufA);
    sum_kernel    <<<blocksM, T>>>(bufA, ptrs3, out);
}